// round 1
// baseline (speedup 1.0000x reference)
#include <cuda_runtime.h>
#include <math.h>

#define N_DRUG   8000
#define N_DIS    20000
#define DDIM     128
#define E_DD     2048
#define E_NN     1000000
#define JSPLIT   14
#define NJT      313            /* ceil(20000/64) */
#define NDIS_PAD 20032          /* padded cols of transposed matrix */

/* ---------------- device scratch (no allocations allowed) ---------------- */
__device__ float g_inv_norm[N_DIS];
__device__ float g_nd [N_DIS * DDIM];       /* normalized h_disease, row-major */
__device__ float g_ndT[DDIM * NDIS_PAD];    /* normalized, transposed [k][j]   */
__device__ float g_cand_val[E_DD * JSPLIT * 3];
__device__ int   g_cand_idx[E_DD * JSPLIT * 3];

/* ---------------- top-3 insert (desc value; ties keep earlier) ----------- */
__device__ __forceinline__ void ins3(float v, int id,
                                     float &v0, int &i0,
                                     float &v1, int &i1,
                                     float &v2, int &i2) {
    if (v > v0)      { v2 = v1; i2 = i1; v1 = v0; i1 = i0; v0 = v; i0 = id; }
    else if (v > v1) { v2 = v1; i2 = i1; v1 = v;  i1 = id; }
    else if (v > v2) { v2 = v;  i2 = id; }
}

/* ================= kernel 1a: per-row 1/(||x||+eps) ====================== */
__global__ void k_inv_norm(const float* __restrict__ hd) {
    int w    = (blockIdx.x * blockDim.x + threadIdx.x) >> 5;
    int lane = threadIdx.x & 31;
    if (w >= N_DIS) return;
    float4 v = ((const float4*)hd)[w * 32 + lane];
    float ss = v.x*v.x + v.y*v.y + v.z*v.z + v.w*v.w;
    #pragma unroll
    for (int o = 16; o; o >>= 1) ss += __shfl_xor_sync(0xffffffffu, ss, o);
    if (lane == 0) g_inv_norm[w] = 1.0f / (sqrtf(ss) + 1e-8f);
}

/* ====== kernel 1b: write normalized row-major AND transposed copies ====== */
__global__ void k_norm_transpose(const float* __restrict__ hd) {
    __shared__ float s[32][132];
    int i0 = blockIdx.x * 32;
    int t  = threadIdx.x;
    for (int idx = t; idx < 32 * 32; idx += 256) {
        int r = idx >> 5, c = idx & 31;
        float  sc = g_inv_norm[i0 + r];
        float4 v  = ((const float4*)hd)[(i0 + r) * 32 + c];
        v.x *= sc; v.y *= sc; v.z *= sc; v.w *= sc;
        ((float4*)g_nd)[(i0 + r) * 32 + c] = v;
        s[r][c*4+0] = v.x; s[r][c*4+1] = v.y; s[r][c*4+2] = v.z; s[r][c*4+3] = v.w;
    }
    __syncthreads();
    for (int idx = t; idx < 128 * 8; idx += 256) {
        int k = idx >> 3, c4 = idx & 7;
        int ii = c4 * 4;
        float4 v = make_float4(s[ii][k], s[ii+1][k], s[ii+2][k], s[ii+3][k]);
        ((float4*)g_ndT)[k * (NDIS_PAD/4) + (i0 >> 2) + c4] = v;
    }
}

/* ======= kernel 2: fused sim-GEMM (64x64 tiles, 4x4/thread) + top-3 ====== */
#define SMEM_Q_F   (64 * 128)      /* 8192 floats  */
#define SMEM_ND_F  (128 * 68)      /* 8704 floats; reused as sim[64][68] */
#define SMEM_BYTES ((SMEM_Q_F + SMEM_ND_F + 256*3) * 4 + 256*3*4 + 64*4)

__global__ void __launch_bounds__(256) k_gemm_topk(const int* __restrict__ dst_dd) {
    extern __shared__ float sm[];
    float* q_s  = sm;                       /* [64][128]                */
    float* nd_s = sm + SMEM_Q_F;            /* [128][68] -> sim[64][68] */
    float* pt_v = nd_s + SMEM_ND_F;         /* [256][3]                 */
    int*   pt_i = (int*)(pt_v + 256 * 3);   /* [256][3]                 */
    int*   sdst = pt_i + 256 * 3;           /* [64]                     */

    const int t  = threadIdx.x;
    const int tx = t & 15, ty = t >> 4;
    const int e0 = blockIdx.x * 64;

    if (t < 64) sdst[t] = dst_dd[e0 + t];
    __syncthreads();
    for (int idx = t; idx < 64 * 32; idx += 256) {       /* load 64 query rows */
        int r = idx >> 5, c = idx & 31;
        ((float4*)q_s)[r * 32 + c] = ((const float4*)g_nd)[sdst[r] * 32 + c];
    }

    float tv0 = -1e30f, tv1 = -1e30f, tv2 = -1e30f;      /* running top3 (t<64) */
    int   ti0 = -1, ti1 = -1, ti2 = -1;

    const float4* q4 = (const float4*)q_s;

    for (int jt = blockIdx.y; jt < NJT; jt += JSPLIT) {
        const int j0 = jt * 64;
        __syncthreads();                                  /* nd_s free to reuse */
        if (j0 + 64 <= N_DIS) {
            for (int idx = t; idx < 128 * 16; idx += 256) {
                int k = idx >> 4, c4 = idx & 15;
                float4 v = ((const float4*)g_ndT)[k * (NDIS_PAD/4) + (j0 >> 2) + c4];
                *(float4*)(nd_s + k * 68 + c4 * 4) = v;
            }
        } else {
            for (int idx = t; idx < 128 * 16; idx += 256) {
                int k = idx >> 4, c4 = idx & 15;
                int j = j0 + c4 * 4;
                float4 v;
                v.x = (j + 0 < N_DIS) ? g_ndT[k * NDIS_PAD + j + 0] : 0.f;
                v.y = (j + 1 < N_DIS) ? g_ndT[k * NDIS_PAD + j + 1] : 0.f;
                v.z = (j + 2 < N_DIS) ? g_ndT[k * NDIS_PAD + j + 2] : 0.f;
                v.w = (j + 3 < N_DIS) ? g_ndT[k * NDIS_PAD + j + 3] : 0.f;
                *(float4*)(nd_s + k * 68 + c4 * 4) = v;
            }
        }
        __syncthreads();

        float acc[4][4];
        #pragma unroll
        for (int e = 0; e < 4; e++)
            #pragma unroll
            for (int j = 0; j < 4; j++) acc[e][j] = 0.f;

        #pragma unroll 8
        for (int k4 = 0; k4 < 32; ++k4) {
            const float4 a0 = q4[(ty*4 + 0) * 32 + k4];
            const float4 a1 = q4[(ty*4 + 1) * 32 + k4];
            const float4 a2 = q4[(ty*4 + 2) * 32 + k4];
            const float4 a3 = q4[(ty*4 + 3) * 32 + k4];
            const float4 b0 = *(const float4*)(nd_s + (k4*4 + 0) * 68 + tx * 4);
            const float4 b1 = *(const float4*)(nd_s + (k4*4 + 1) * 68 + tx * 4);
            const float4 b2 = *(const float4*)(nd_s + (k4*4 + 2) * 68 + tx * 4);
            const float4 b3 = *(const float4*)(nd_s + (k4*4 + 3) * 68 + tx * 4);
            #define MM_ROW(E, AE)                                              \
                acc[E][0] += AE.x*b0.x + AE.y*b1.x + AE.z*b2.x + AE.w*b3.x;    \
                acc[E][1] += AE.x*b0.y + AE.y*b1.y + AE.z*b2.y + AE.w*b3.y;    \
                acc[E][2] += AE.x*b0.z + AE.y*b1.z + AE.z*b2.z + AE.w*b3.z;    \
                acc[E][3] += AE.x*b0.w + AE.y*b1.w + AE.z*b2.w + AE.w*b3.w;
            MM_ROW(0, a0) MM_ROW(1, a1) MM_ROW(2, a2) MM_ROW(3, a3)
            #undef MM_ROW
        }
        __syncthreads();                                  /* done reading nd_s */
        #pragma unroll
        for (int e = 0; e < 4; e++)
            *(float4*)(nd_s + (ty*4 + e) * 68 + tx * 4) =
                make_float4(acc[e][0], acc[e][1], acc[e][2], acc[e][3]);
        __syncthreads();

        {   /* partial top3: 4 threads per edge, 16 j each */
            int e = t >> 2, p = t & 3;
            float v0 = -1e30f, v1 = -1e30f, v2 = -1e30f;
            int   a0 = -1, a1 = -1, a2 = -1;
            int   myDst = sdst[e];
            #pragma unroll
            for (int jj = 0; jj < 16; jj++) {
                int j  = p * 16 + jj;
                int jg = j0 + j;
                float sv = nd_s[e * 68 + j];
                if (jg < N_DIS && jg != myDst)
                    ins3(sv, jg, v0, a0, v1, a1, v2, a2);
            }
            pt_v[t*3+0] = v0; pt_v[t*3+1] = v1; pt_v[t*3+2] = v2;
            pt_i[t*3+0] = a0; pt_i[t*3+1] = a1; pt_i[t*3+2] = a2;
        }
        __syncthreads();
        if (t < 64) {
            #pragma unroll
            for (int p = 0; p < 4; p++)
                #pragma unroll
                for (int s = 0; s < 3; s++) {
                    float v  = pt_v[(t*4 + p)*3 + s];
                    int   id = pt_i[(t*4 + p)*3 + s];
                    if (id >= 0) ins3(v, id, tv0, ti0, tv1, ti1, tv2, ti2);
                }
        }
    }
    if (t < 64) {
        int base = ((e0 + t) * JSPLIT + blockIdx.y) * 3;
        g_cand_val[base+0] = tv0; g_cand_idx[base+0] = ti0;
        g_cand_val[base+1] = tv1; g_cand_idx[base+1] = ti1;
        g_cand_val[base+2] = tv2; g_cand_idx[base+2] = ti2;
    }
}

/* ==== kernel 3: merge candidates, softmax, prototype, score_dd =========== */
__global__ void k_score_dd(const float* __restrict__ h_drug,
                           const float* __restrict__ h_dis,
                           const float* __restrict__ W,
                           const int*   __restrict__ src_dd,
                           const int*   __restrict__ dst_dd,
                           const int*   __restrict__ deg,
                           float*       __restrict__ out) {
    int e    = (blockIdx.x * blockDim.x + threadIdx.x) >> 5;
    int lane = threadIdx.x & 31;
    if (e >= E_DD) return;

    float w0 = 0.f, w1 = 0.f, w2 = 0.f;
    int   i0 = 0, i1 = 0, i2 = 0;
    if (lane == 0) {
        float v0 = -1e30f, v1 = -1e30f, v2 = -1e30f;
        int   a0 = -1, a1 = -1, a2 = -1;
        #pragma unroll 6
        for (int c = 0; c < JSPLIT * 3; c++) {
            float v  = g_cand_val[e * JSPLIT * 3 + c];
            int   id = g_cand_idx[e * JSPLIT * 3 + c];
            if (id >= 0) ins3(v, id, v0, a0, v1, a1, v2, a2);
        }
        float x1 = expf(v1 - v0), x2 = expf(v2 - v0);
        float s  = 1.f + x1 + x2;
        w0 = 1.f / s; w1 = x1 / s; w2 = x2 / s;
        i0 = a0; i1 = a1; i2 = a2;
    }
    w0 = __shfl_sync(0xffffffffu, w0, 0);
    w1 = __shfl_sync(0xffffffffu, w1, 0);
    w2 = __shfl_sync(0xffffffffu, w2, 0);
    i0 = __shfl_sync(0xffffffffu, i0, 0);
    i1 = __shfl_sync(0xffffffffu, i1, 0);
    i2 = __shfl_sync(0xffffffffu, i2, 0);

    int   sidx = src_dd[e], didx = dst_dd[e];
    float coef = expf(-0.7f * (float)deg[didx]);
    float om   = 1.f - coef;

    float4 sv = ((const float4*)h_drug)[sidx * 32 + lane];
    float4 wv = ((const float4*)W)[lane];            /* W row 0 */
    float4 dv = ((const float4*)h_dis)[didx * 32 + lane];
    float4 p0 = ((const float4*)h_dis)[i0 * 32 + lane];
    float4 p1 = ((const float4*)h_dis)[i1 * 32 + lane];
    float4 p2 = ((const float4*)h_dis)[i2 * 32 + lane];

    float r =
        sv.x * wv.x * (om * dv.x + coef * (w0*p0.x + w1*p1.x + w2*p2.x)) +
        sv.y * wv.y * (om * dv.y + coef * (w0*p0.y + w1*p1.y + w2*p2.y)) +
        sv.z * wv.z * (om * dv.z + coef * (w0*p0.z + w1*p1.z + w2*p2.z)) +
        sv.w * wv.w * (om * dv.w + coef * (w0*p0.w + w1*p1.w + w2*p2.w));
    #pragma unroll
    for (int o = 16; o; o >>= 1) r += __shfl_xor_sync(0xffffffffu, r, o);
    if (lane == 0) out[e] = r;
}

/* ==== kernel 4: score_nn — warp per edge, L2-resident gather-dot ========= */
__global__ void k_score_nn(const float* __restrict__ h_dis,
                           const float* __restrict__ W,
                           const int*   __restrict__ src,
                           const int*   __restrict__ dst,
                           float*       __restrict__ out) {
    int e    = (int)((blockIdx.x * (unsigned)blockDim.x + threadIdx.x) >> 5);
    int lane = threadIdx.x & 31;
    if (e >= E_NN) return;
    int s = __ldg(src + e), d = __ldg(dst + e);
    float4 a = ((const float4*)h_dis)[s * 32 + lane];
    float4 b = ((const float4*)h_dis)[d * 32 + lane];
    float4 w = ((const float4*)W)[32 + lane];        /* W row 1 */
    float r = a.x*w.x*b.x + a.y*w.y*b.y + a.z*w.z*b.z + a.w*w.w*b.w;
    #pragma unroll
    for (int o = 16; o; o >>= 1) r += __shfl_xor_sync(0xffffffffu, r, o);
    if (lane == 0) out[E_DD + e] = r;
}

/* ========================================================================= */
extern "C" void kernel_launch(void* const* d_in, const int* in_sizes, int n_in,
                              void* d_out, int out_size) {
    const float* h_drug = (const float*)d_in[0];
    const float* h_dis  = (const float*)d_in[1];
    const float* W      = (const float*)d_in[2];
    const int*   src_dd = (const int*)d_in[3];
    const int*   dst_dd = (const int*)d_in[4];
    const int*   src_nn = (const int*)d_in[5];
    const int*   dst_nn = (const int*)d_in[6];
    const int*   deg    = (const int*)d_in[7];
    float* out = (float*)d_out;

    cudaFuncSetAttribute(k_gemm_topk,
                         cudaFuncAttributeMaxDynamicSharedMemorySize, SMEM_BYTES);

    /* big memory-bound kernel first */
    k_score_nn<<<(E_NN * 32 + 255) / 256, 256>>>(h_dis, W, src_nn, dst_nn, out);

    k_inv_norm<<<(N_DIS * 32 + 255) / 256, 256>>>(h_dis);
    k_norm_transpose<<<N_DIS / 32, 256>>>(h_dis);
    k_gemm_topk<<<dim3(E_DD / 64, JSPLIT), 256, SMEM_BYTES>>>(dst_dd);
    k_score_dd<<<(E_DD * 32 + 255) / 256, 256>>>(h_drug, h_dis, W,
                                                 src_dd, dst_dd, deg, out);
}